// round 14
// baseline (speedup 1.0000x reference)
#include <cuda_runtime.h>
#include <cuda_bf16.h>
#include <math.h>
#include <cstdint>

#define NN 50000
#define NE 800000
#define D  128
#define NEG 0.2f
#define BNEPS 1e-5f
#define SB 196   // scan blocks (196*256 = 50176 >= NN)

// ---------------- static device scratch (no allocations allowed) ----------------
__device__ float g_xl[NN * D];
__device__ float g_xr[NN * D];
__device__ float g_out[NN * D];
__device__ __nv_bfloat16 g_whi[3 * 2 * D * D];   // W^T per layer/matrix: [lm][n][k]
__device__ __nv_bfloat16 g_wlo[3 * 2 * D * D];
__device__ int   g_srcs[NE];
__device__ int   g_off[NN + 1];
__device__ int   g_cur[NN];
__device__ int   g_cnt[NN];
__device__ int   g_part[256];
__device__ float g_stat[3][2][8][128];  // [layer][sum|sq][copy][col]
__device__ int   g_is64;

// ---------------- edge dtype probe + zeroing (fused) ----------------
__global__ void k_detect_zero(const int* __restrict__ w) {
    int i = blockIdx.x * 256 + threadIdx.x;
    if (i < NN) g_cnt[i] = 0;
    if (i < 3 * 2 * 8 * 128) ((float*)g_stat)[i] = 0.f;
    if (i == 0) {
        int allz = 1;
        for (int j = 1; j < 64; j += 2)
            if (w[j] != 0) allz = 0;
        g_is64 = allz;
    }
}

__device__ __forceinline__ int edge_at(const int* __restrict__ w, int pos, int is64) {
    return is64 ? w[(long long)pos * 2] : w[pos];
}

// ---------------- CSR build ----------------
__global__ void k_hist(const int* __restrict__ ei) {
    int e = blockIdx.x * 256 + threadIdx.x;
    if (e < NE) atomicAdd(&g_cnt[edge_at(ei, NE + e, g_is64)], 1);
}

__global__ void k_part() {
    __shared__ int sh[256];
    int tid = threadIdx.x;
    int i = blockIdx.x * 256 + tid;
    int v = (i < NN) ? g_cnt[i] : 0;
    sh[tid] = v;
    __syncthreads();
    for (int o = 128; o > 0; o >>= 1) {
        if (tid < o) sh[tid] += sh[tid + o];
        __syncthreads();
    }
    if (tid == 0) g_part[blockIdx.x] = sh[0];
}

__global__ void k_scanpart() {
    __shared__ int sh[256];
    int tid = threadIdx.x;
    int v = (tid < SB) ? g_part[tid] : 0;
    sh[tid] = v;
    __syncthreads();
    for (int o = 1; o < 256; o <<= 1) {
        int t = (tid >= o) ? sh[tid - o] : 0;
        __syncthreads();
        sh[tid] += t;
        __syncthreads();
    }
    g_part[tid] = sh[tid] - v;
}

__global__ void k_off() {
    __shared__ int sh[256];
    int tid = threadIdx.x;
    int i = blockIdx.x * 256 + tid;
    int v = (i < NN) ? g_cnt[i] : 0;
    sh[tid] = v;
    __syncthreads();
    for (int o = 1; o < 256; o <<= 1) {
        int t = (tid >= o) ? sh[tid - o] : 0;
        __syncthreads();
        sh[tid] += t;
        __syncthreads();
    }
    int excl = sh[tid] - v + g_part[blockIdx.x];
    if (i < NN) {
        g_off[i] = excl;
        g_cur[i] = excl;
        if (i == NN - 1) g_off[NN] = excl + v;
    }
}

__global__ void k_scatter(const int* __restrict__ ei) {
    int e = blockIdx.x * 256 + threadIdx.x;
    if (e < NE) {
        int is64 = g_is64;
        int src = edge_at(ei, e, is64);
        int dst = edge_at(ei, NE + e, is64);
        int pos = atomicAdd(&g_cur[dst], 1);
        g_srcs[pos] = src;
    }
}

// ---------------- conversions (fp32 -> split bf16) ----------------
__device__ __forceinline__ void split2(float a, float b, uint32_t& hi, uint32_t& lo) {
    __nv_bfloat16 ha = __float2bfloat16(a);
    __nv_bfloat16 hb = __float2bfloat16(b);
    __nv_bfloat16 la = __float2bfloat16(a - __bfloat162float(ha));
    __nv_bfloat16 lb = __float2bfloat16(b - __bfloat162float(hb));
    hi = (uint32_t)__bfloat16_as_ushort(ha) | ((uint32_t)__bfloat16_as_ushort(hb) << 16);
    lo = (uint32_t)__bfloat16_as_ushort(la) | ((uint32_t)__bfloat16_as_ushort(lb) << 16);
}

// W^T split: wt[lm][n][k] = W[l][k][n]   (lm = l*2+m; m: 0=Wl, 1=Wr)
__global__ void k_cvt_w(const float* __restrict__ Wl, const float* __restrict__ Wr) {
    int idx = blockIdx.x * 256 + threadIdx.x;
    if (idx >= 3 * 2 * D * D) return;
    int lm = idx >> 14, r = idx & 16383;
    int n = r >> 7, k = r & 127;
    int l = lm >> 1, m = lm & 1;
    const float* W = m ? Wr : Wl;
    float v = W[l * D * D + k * D + n];
    __nv_bfloat16 h = __float2bfloat16(v);
    __nv_bfloat16 lo = __float2bfloat16(v - __bfloat162float(h));
    g_whi[idx] = h;
    g_wlo[idx] = lo;
}

// ---------------- tensor-core dual GEMM: fused BN/GELU/split A-stage + cp.async B ----------------
__device__ __forceinline__ void mma16816(float* c, const uint32_t* a, const uint32_t* b) {
    asm volatile(
        "mma.sync.aligned.m16n8k16.row.col.f32.bf16.bf16.f32 "
        "{%0,%1,%2,%3}, {%4,%5,%6,%7}, {%8,%9}, {%0,%1,%2,%3};"
        : "+f"(c[0]), "+f"(c[1]), "+f"(c[2]), "+f"(c[3])
        : "r"(a[0]), "r"(a[1]), "r"(a[2]), "r"(a[3]), "r"(b[0]), "r"(b[1]));
}

__device__ __forceinline__ void ldsm4(uint32_t* r, uint32_t addr) {
    asm volatile(
        "ldmatrix.sync.aligned.m8n8.x4.shared.b16 {%0,%1,%2,%3}, [%4];"
        : "=r"(r[0]), "=r"(r[1]), "=r"(r[2]), "=r"(r[3]) : "r"(addr));
}

__device__ __forceinline__ void cp16(uint32_t dst, const void* src, int sz) {
    asm volatile("cp.async.cg.shared.global [%0], [%1], 16, %2;"
                 :: "r"(dst), "l"(src), "r"(sz));
}
#define CP_COMMIT() asm volatile("cp.async.commit_group;")
#define CP_WAIT0()  asm volatile("cp.async.wait_group 0;" ::: "memory")

// smem: A_hi[128][256B] @0, A_lo @32KB, B tiles @64KB (Wl_hi, Wl_lo, Wr_hi, Wr_lo),
// stats @192KB (scale[128], shift[128]).
#define GEMM_SMEM (196608 + 1024)

// l==0: A rows come from xin (plain split). l>0: A rows = gelu(BN(g_out)) with
// stats from g_stat[l-1] and gamma/beta of layer l-1, then split.
__global__ void __launch_bounds__(512, 1) k_gemm_mma(int l, const float* __restrict__ xin,
                                                     const float* __restrict__ gamma,
                                                     const float* __restrict__ beta) {
    extern __shared__ __align__(16) char sm[];
    float* sstat = (float*)(sm + 196608);
    int tid = threadIdx.x;
    int row0 = blockIdx.x * 128;
    uint32_t sbase = (uint32_t)__cvta_generic_to_shared(sm);

    // B first (async, flies under A compute): 4 tiles, each 128 n-rows x 16 chunks
    for (int i = tid; i < 8192; i += 512) {
        int tile = i >> 11, j = i & 2047;
        int n = j >> 4, c = j & 15;
        int mm = tile >> 1;
        const __nv_bfloat16* src = (tile & 1) ? g_wlo : g_whi;
        uint32_t soff = (uint32_t)(65536 + tile * 32768 + n * 256 + ((c ^ (n & 7)) << 4));
        cp16(sbase + soff, src + ((l * 2 + mm) * D + n) * D + c * 8, 16);
    }
    CP_COMMIT();

    // BN stats -> smem (scale/shift per column), summing 8 atomic copies
    if (l > 0) {
        if (tid < 128) {
            float s = 0.f, q = 0.f;
#pragma unroll
            for (int c = 0; c < 8; c++) {
                s += g_stat[l - 1][0][c][tid];
                q += g_stat[l - 1][1][c][tid];
            }
            const float invN = 1.f / (float)NN;
            float mu = s * invN;
            float var = q * invN - mu * mu;
            float sc = gamma[tid] * rsqrtf(var + BNEPS);
            sstat[tid] = sc;
            sstat[128 + tid] = beta[tid] - mu * sc;
        }
        __syncthreads();
    }

    // A stage: 4 chunks/thread; batch all 8 float4 loads first (MLP=8), then compute+STS
    const float* asrc = (l == 0) ? xin : g_out;
    {
        float4 va[4], vb[4];
#pragma unroll
        for (int k = 0; k < 4; k++) {
            int i = tid + 512 * k;
            int r = i >> 4, c = i & 15;
            int gr = row0 + r;
            if (gr < NN) {
                const float4* sp = (const float4*)(asrc + gr * D + c * 8);
                va[k] = sp[0];
                vb[k] = sp[1];
            } else {
                va[k] = make_float4(0.f, 0.f, 0.f, 0.f);
                vb[k] = make_float4(0.f, 0.f, 0.f, 0.f);
            }
        }
#pragma unroll
        for (int k = 0; k < 4; k++) {
            int i = tid + 512 * k;
            int r = i >> 4, c = i & 15;
            float e[8] = {va[k].x, va[k].y, va[k].z, va[k].w,
                          vb[k].x, vb[k].y, vb[k].z, vb[k].w};
            if (l > 0) {
                int col = c * 8;
#pragma unroll
                for (int j = 0; j < 8; j++) {
                    float y = fmaf(e[j], sstat[col + j], sstat[128 + col + j]);
                    e[j] = 0.5f * y * (1.f + erff(y * 0.70710678118654752f));
                }
            }
            uint4 hi, lo;
            split2(e[0], e[1], hi.x, lo.x);
            split2(e[2], e[3], hi.y, lo.y);
            split2(e[4], e[5], hi.z, lo.z);
            split2(e[6], e[7], hi.w, lo.w);
            uint32_t soff = (uint32_t)(r * 256 + ((c ^ (r & 7)) << 4));
            *(uint4*)(sm + soff) = hi;
            *(uint4*)(sm + 32768 + soff) = lo;
        }
    }
    CP_WAIT0();
    __syncthreads();

    int wid = tid >> 5, lane = tid & 31;
    int rg = wid & 3;          // row group: rows rg*32 .. rg*32+31
    int cg = wid >> 2;         // col group: 0,1 -> xl ; 2,3 -> xr
    int m = cg >> 1;
    int colbase = (cg & 1) * 64;
    uint32_t sA_h = sbase;
    uint32_t sA_l = sbase + 32768;
    uint32_t sB_h = sbase + 65536 + (uint32_t)(m * 2) * 32768u;
    uint32_t sB_l = sB_h + 32768;

    float acc[2][8][4];
#pragma unroll
    for (int mt = 0; mt < 2; mt++)
#pragma unroll
        for (int nt = 0; nt < 8; nt++)
#pragma unroll
            for (int q = 0; q < 4; q++) acc[mt][nt][q] = 0.f;

    // ldmatrix lane address components
    int a_r = (lane & 7) + ((lane >> 3) & 1) * 8;
    int a_c = lane >> 4;
    int b_n = (lane & 7) + (lane >> 4) * 8;
    int b_c = (lane >> 3) & 1;

#pragma unroll
    for (int ks = 0; ks < 8; ks++) {
        uint32_t ah[2][4], al[2][4];
#pragma unroll
        for (int mt = 0; mt < 2; mt++) {
            int r = rg * 32 + mt * 16 + a_r;
            int c = 2 * ks + a_c;
            uint32_t off = (uint32_t)(r * 256 + ((c ^ (r & 7)) << 4));
            ldsm4(ah[mt], sA_h + off);
            ldsm4(al[mt], sA_l + off);
        }
#pragma unroll
        for (int ng = 0; ng < 4; ng++) {
            int n = colbase + ng * 16 + b_n;
            int c = 2 * ks + b_c;
            uint32_t off = (uint32_t)(n * 256 + ((c ^ (n & 7)) << 4));
            uint32_t bh[4], bl[4];
            ldsm4(bh, sB_h + off);
            ldsm4(bl, sB_l + off);
            // term-outer order: same-acc dependency gap = 4 HMMA
            mma16816(acc[0][2 * ng], ah[0], &bh[0]);
            mma16816(acc[0][2 * ng + 1], ah[0], &bh[2]);
            mma16816(acc[1][2 * ng], ah[1], &bh[0]);
            mma16816(acc[1][2 * ng + 1], ah[1], &bh[2]);
            mma16816(acc[0][2 * ng], ah[0], &bl[0]);
            mma16816(acc[0][2 * ng + 1], ah[0], &bl[2]);
            mma16816(acc[1][2 * ng], ah[1], &bl[0]);
            mma16816(acc[1][2 * ng + 1], ah[1], &bl[2]);
            mma16816(acc[0][2 * ng], al[0], &bh[0]);
            mma16816(acc[0][2 * ng + 1], al[0], &bh[2]);
            mma16816(acc[1][2 * ng], al[1], &bh[0]);
            mma16816(acc[1][2 * ng + 1], al[1], &bh[2]);
        }
    }

    float* dst = m ? g_xr : g_xl;
    int g = lane >> 2, t = lane & 3;
#pragma unroll
    for (int mt = 0; mt < 2; mt++) {
#pragma unroll
        for (int nt = 0; nt < 8; nt++) {
            int r0 = row0 + rg * 32 + mt * 16 + g;
            int cc = colbase + nt * 8 + 2 * t;
            if (r0 < NN)
                *(float2*)(dst + r0 * D + cc) = make_float2(acc[mt][nt][0], acc[mt][nt][1]);
            if (r0 + 8 < NN)
                *(float2*)(dst + (r0 + 8) * D + cc) = make_float2(acc[mt][nt][2], acc[mt][nt][3]);
        }
    }
}

// ---------------- per-node GATv2 + fused BN stat accumulation ----------------
__device__ __forceinline__ float lrelu(float z) {
    return z > 0.f ? z : NEG * z;
}

__global__ void __launch_bounds__(64) k_node(int l, const float* __restrict__ att,
                                             const float* __restrict__ bias) {
    int node = blockIdx.x * 2 + (threadIdx.x >> 5);
    if (node >= NN) return;
    int lane = threadIdx.x & 31;
    int l16 = lane & 15;
    int grp = lane >> 4;
    const unsigned gmask = 0xFFFFu << (grp << 4);
    int beg = g_off[node], end = g_off[node + 1];

    const float4* xr4 = (const float4*)(g_xr + node * 128 + l16 * 8);
    float4 xr0 = xr4[0], xr1 = xr4[1];
    const float4* at4 = (const float4*)(att + l16 * 8);
    float4 a0 = at4[0], a1 = at4[1];

    float m = -1e30f, sum = 0.f;
    float4 acc0 = make_float4(0.f, 0.f, 0.f, 0.f);
    float4 acc1 = make_float4(0.f, 0.f, 0.f, 0.f);

    for (int p = beg + grp; p < end; p += 2) {
        int s = g_srcs[p];
        const float4* v4 = (const float4*)(g_xl + s * 128 + l16 * 8);
        float4 v0 = v4[0], v1 = v4[1];
        float d = lrelu(v0.x + xr0.x) * a0.x;
        d = fmaf(lrelu(v0.y + xr0.y), a0.y, d);
        d = fmaf(lrelu(v0.z + xr0.z), a0.z, d);
        d = fmaf(lrelu(v0.w + xr0.w), a0.w, d);
        d = fmaf(lrelu(v1.x + xr1.x), a1.x, d);
        d = fmaf(lrelu(v1.y + xr1.y), a1.y, d);
        d = fmaf(lrelu(v1.z + xr1.z), a1.z, d);
        d = fmaf(lrelu(v1.w + xr1.w), a1.w, d);
#pragma unroll
        for (int o = 1; o < 16; o <<= 1) d += __shfl_xor_sync(gmask, d, o);
        float mn = fmaxf(m, d);
        float c = __expf(m - mn);
        float w = __expf(d - mn);
        sum = sum * c + w;
        acc0.x = fmaf(acc0.x, c, w * v0.x);
        acc0.y = fmaf(acc0.y, c, w * v0.y);
        acc0.z = fmaf(acc0.z, c, w * v0.z);
        acc0.w = fmaf(acc0.w, c, w * v0.w);
        acc1.x = fmaf(acc1.x, c, w * v1.x);
        acc1.y = fmaf(acc1.y, c, w * v1.y);
        acc1.z = fmaf(acc1.z, c, w * v1.z);
        acc1.w = fmaf(acc1.w, c, w * v1.w);
        m = mn;
    }
    __syncwarp();
    float mo = __shfl_xor_sync(0xffffffffu, m, 16);
    float so = __shfl_xor_sync(0xffffffffu, sum, 16);
    float ms = fmaxf(m, mo);
    float cme = __expf(m - ms);
    float sum_t = fmaf(so, __expf(mo - ms), sum * cme);
    acc0.x *= cme; acc0.y *= cme; acc0.z *= cme; acc0.w *= cme;
    acc1.x *= cme; acc1.y *= cme; acc1.z *= cme; acc1.w *= cme;
    acc0.x += __shfl_xor_sync(0xffffffffu, acc0.x, 16);
    acc0.y += __shfl_xor_sync(0xffffffffu, acc0.y, 16);
    acc0.z += __shfl_xor_sync(0xffffffffu, acc0.z, 16);
    acc0.w += __shfl_xor_sync(0xffffffffu, acc0.w, 16);
    acc1.x += __shfl_xor_sync(0xffffffffu, acc1.x, 16);
    acc1.y += __shfl_xor_sync(0xffffffffu, acc1.y, 16);
    acc1.z += __shfl_xor_sync(0xffffffffu, acc1.z, 16);
    acc1.w += __shfl_xor_sync(0xffffffffu, acc1.w, 16);
    if (grp == 0) {
        float inv = 1.f / (sum_t + 1e-16f);
        const float4* b4 = (const float4*)(bias + l16 * 8);
        float4 b0 = b4[0], b1 = b4[1];
        float o[8];
        o[0] = fmaf(acc0.x, inv, b0.x);
        o[1] = fmaf(acc0.y, inv, b0.y);
        o[2] = fmaf(acc0.z, inv, b0.z);
        o[3] = fmaf(acc0.w, inv, b0.w);
        o[4] = fmaf(acc1.x, inv, b1.x);
        o[5] = fmaf(acc1.y, inv, b1.y);
        o[6] = fmaf(acc1.z, inv, b1.z);
        o[7] = fmaf(acc1.w, inv, b1.w);
        float4* op = (float4*)(g_out + node * 128 + l16 * 8);
        op[0] = make_float4(o[0], o[1], o[2], o[3]);
        op[1] = make_float4(o[4], o[5], o[6], o[7]);
        // fused BN stat accumulation (8 copies to spread atomic contention)
        int cp = blockIdx.x & 7;
        float* st = g_stat[l][0][cp];
        float* sq = g_stat[l][1][cp];
        int col = l16 * 8;
#pragma unroll
        for (int j = 0; j < 8; j++) {
            atomicAdd(&st[col + j], o[j]);
            atomicAdd(&sq[col + j], o[j] * o[j]);
        }
    }
}

// final-layer BN + erf-GELU -> fp32 d_out
__global__ void k_bnapply(const float* __restrict__ gamma,
                          const float* __restrict__ beta,
                          float* __restrict__ dptr) {
    __shared__ float ssc[128], ssh[128];
    int tid = threadIdx.x;
    if (tid < 128) {
        float s = 0.f, q = 0.f;
#pragma unroll
        for (int c = 0; c < 8; c++) {
            s += g_stat[2][0][c][tid];
            q += g_stat[2][1][c][tid];
        }
        const float invN = 1.f / (float)NN;
        float mu = s * invN;
        float var = q * invN - mu * mu;
        float sc = gamma[tid] * rsqrtf(var + BNEPS);
        ssc[tid] = sc;
        ssh[tid] = beta[tid] - mu * sc;
    }
    __syncthreads();
    int i = blockIdx.x * 256 + tid;  // over NN*32 float4s
    if (i >= NN * 32) return;
    int c4 = (i & 31) * 4;
    float4 v = ((const float4*)g_out)[i];
    float o[4];
    float vin[4] = {v.x, v.y, v.z, v.w};
#pragma unroll
    for (int c = 0; c < 4; c++) {
        float y = fmaf(vin[c], ssc[c4 + c], ssh[c4 + c]);
        o[c] = 0.5f * y * (1.f + erff(y * 0.70710678118654752f));
    }
    ((float4*)dptr)[i] = make_float4(o[0], o[1], o[2], o[3]);
}

// ---------------- launch ----------------
extern "C" void kernel_launch(void* const* d_in, const int* in_sizes, int n_in,
                              void* d_out, int out_size) {
    const float* x = (const float*)d_in[0];
    const int* ei = (const int*)d_in[1];
    const float* Wl = (const float*)d_in[2];
    const float* Wr = (const float*)d_in[3];
    const float* att = (const float*)d_in[4];
    const float* bias = (const float*)d_in[5];
    const float* gamma = (const float*)d_in[6];
    const float* beta = (const float*)d_in[7];
    float* outp = (float*)d_out;

    cudaFuncSetAttribute(k_gemm_mma, cudaFuncAttributeMaxDynamicSharedMemorySize, GEMM_SMEM);

    const int gemm_blocks = (NN + 127) / 128;

    // launches 1-3: cvt_w, detect+zero, hist; 4: layer-0 GEMM (profiled slot)
    k_cvt_w<<<(3 * 2 * D * D + 255) / 256, 256>>>(Wl, Wr);
    k_detect_zero<<<SB, 256>>>(ei);
    k_hist<<<(NE + 255) / 256, 256>>>(ei);
    k_gemm_mma<<<gemm_blocks, 512, GEMM_SMEM>>>(0, x, nullptr, nullptr);

    // CSR by dst (remaining stages)
    k_part<<<SB, 256>>>();
    k_scanpart<<<1, 256>>>();
    k_off<<<SB, 256>>>();
    k_scatter<<<(NE + 255) / 256, 256>>>(ei);

    for (int l = 0; l < 3; l++) {
        if (l > 0)
            k_gemm_mma<<<gemm_blocks, 512, GEMM_SMEM>>>(l, nullptr,
                                                        gamma + (l - 1) * D,
                                                        beta + (l - 1) * D);
        k_node<<<(NN + 1) / 2, 64>>>(l, att + l * D, bias + l * D);
    }
    // final BN+GELU -> output
    k_bnapply<<<(NN * 32 + 255) / 256, 256>>>(gamma + 2 * D, beta + 2 * D, outp);
}

// round 15
// speedup vs baseline: 4.3951x; 4.3951x over previous
#include <cuda_runtime.h>
#include <cuda_bf16.h>
#include <math.h>
#include <cstdint>

#define NN 50000
#define NE 800000
#define D  128
#define NEG 0.2f
#define BNEPS 1e-5f
#define SB 196   // scan blocks (196*256 = 50176 >= NN)

// ---------------- static device scratch (no allocations allowed) ----------------
__device__ float g_xl[NN * D];
__device__ float g_xr[NN * D];
__device__ float g_out[NN * D];
__device__ __nv_bfloat16 g_whi[3 * 2 * D * D];   // W^T per layer/matrix: [lm][n][k]
__device__ __nv_bfloat16 g_wlo[3 * 2 * D * D];
__device__ int   g_srcs[NE];
__device__ int   g_off[NN + 1];
__device__ int   g_cur[NN];
__device__ int   g_cnt[NN];
__device__ int   g_part[256];
__device__ float g_colsum[D];
__device__ float g_colsq[D];
__device__ int   g_is64;

// ---------------- edge dtype probe + counter zero (fused) ----------------
__global__ void k_detect_zero(const int* __restrict__ w) {
    int i = blockIdx.x * 256 + threadIdx.x;
    if (i < NN) g_cnt[i] = 0;
    if (i == 0) {
        int allz = 1;
        for (int j = 1; j < 64; j += 2)
            if (w[j] != 0) allz = 0;
        g_is64 = allz;
    }
}

__device__ __forceinline__ int edge_at(const int* __restrict__ w, int pos, int is64) {
    return is64 ? w[(long long)pos * 2] : w[pos];
}

// ---------------- CSR build ----------------
__global__ void k_hist(const int* __restrict__ ei) {
    int e = blockIdx.x * 256 + threadIdx.x;
    if (e < NE) atomicAdd(&g_cnt[edge_at(ei, NE + e, g_is64)], 1);
}

__global__ void k_part() {
    __shared__ int sh[256];
    int tid = threadIdx.x;
    int i = blockIdx.x * 256 + tid;
    int v = (i < NN) ? g_cnt[i] : 0;
    sh[tid] = v;
    __syncthreads();
    for (int o = 128; o > 0; o >>= 1) {
        if (tid < o) sh[tid] += sh[tid + o];
        __syncthreads();
    }
    if (tid == 0) g_part[blockIdx.x] = sh[0];
}

__global__ void k_scanpart() {
    __shared__ int sh[256];
    int tid = threadIdx.x;
    int v = (tid < SB) ? g_part[tid] : 0;
    sh[tid] = v;
    __syncthreads();
    for (int o = 1; o < 256; o <<= 1) {
        int t = (tid >= o) ? sh[tid - o] : 0;
        __syncthreads();
        sh[tid] += t;
        __syncthreads();
    }
    g_part[tid] = sh[tid] - v;
}

__global__ void k_off() {
    __shared__ int sh[256];
    int tid = threadIdx.x;
    int i = blockIdx.x * 256 + tid;
    int v = (i < NN) ? g_cnt[i] : 0;
    sh[tid] = v;
    __syncthreads();
    for (int o = 1; o < 256; o <<= 1) {
        int t = (tid >= o) ? sh[tid - o] : 0;
        __syncthreads();
        sh[tid] += t;
        __syncthreads();
    }
    int excl = sh[tid] - v + g_part[blockIdx.x];
    if (i < NN) {
        g_off[i] = excl;
        g_cur[i] = excl;
        if (i == NN - 1) g_off[NN] = excl + v;
    }
}

__global__ void k_scatter(const int* __restrict__ ei) {
    int e = blockIdx.x * 256 + threadIdx.x;
    if (e < NE) {
        int is64 = g_is64;
        int src = edge_at(ei, e, is64);
        int dst = edge_at(ei, NE + e, is64);
        int pos = atomicAdd(&g_cur[dst], 1);
        g_srcs[pos] = src;
    }
}

// ---------------- conversions (fp32 -> split bf16) ----------------
__device__ __forceinline__ void split2(float a, float b, uint32_t& hi, uint32_t& lo) {
    __nv_bfloat16 ha = __float2bfloat16(a);
    __nv_bfloat16 hb = __float2bfloat16(b);
    __nv_bfloat16 la = __float2bfloat16(a - __bfloat162float(ha));
    __nv_bfloat16 lb = __float2bfloat16(b - __bfloat162float(hb));
    hi = (uint32_t)__bfloat16_as_ushort(ha) | ((uint32_t)__bfloat16_as_ushort(hb) << 16);
    lo = (uint32_t)__bfloat16_as_ushort(la) | ((uint32_t)__bfloat16_as_ushort(lb) << 16);
}

// W^T split: wt[lm][n][k] = W[l][k][n]   (lm = l*2+m; m: 0=Wl, 1=Wr)
__global__ void k_cvt_w(const float* __restrict__ Wl, const float* __restrict__ Wr) {
    int idx = blockIdx.x * 256 + threadIdx.x;
    if (idx >= 3 * 2 * D * D) return;
    int lm = idx >> 14, r = idx & 16383;
    int n = r >> 7, k = r & 127;
    int l = lm >> 1, m = lm & 1;
    const float* W = m ? Wr : Wl;
    float v = W[l * D * D + k * D + n];
    __nv_bfloat16 h = __float2bfloat16(v);
    __nv_bfloat16 lo = __float2bfloat16(v - __bfloat162float(h));
    g_whi[idx] = h;
    g_wlo[idx] = lo;
}

// ---------------- tensor-core dual GEMM: fused BN/GELU/split A-stage + cp.async B ----------------
__device__ __forceinline__ void mma16816(float* c, const uint32_t* a, const uint32_t* b) {
    asm volatile(
        "mma.sync.aligned.m16n8k16.row.col.f32.bf16.bf16.f32 "
        "{%0,%1,%2,%3}, {%4,%5,%6,%7}, {%8,%9}, {%0,%1,%2,%3};"
        : "+f"(c[0]), "+f"(c[1]), "+f"(c[2]), "+f"(c[3])
        : "r"(a[0]), "r"(a[1]), "r"(a[2]), "r"(a[3]), "r"(b[0]), "r"(b[1]));
}

__device__ __forceinline__ void ldsm4(uint32_t* r, uint32_t addr) {
    asm volatile(
        "ldmatrix.sync.aligned.m8n8.x4.shared.b16 {%0,%1,%2,%3}, [%4];"
        : "=r"(r[0]), "=r"(r[1]), "=r"(r[2]), "=r"(r[3]) : "r"(addr));
}

__device__ __forceinline__ void cp16(uint32_t dst, const void* src, int sz) {
    asm volatile("cp.async.cg.shared.global [%0], [%1], 16, %2;"
                 :: "r"(dst), "l"(src), "r"(sz));
}
#define CP_COMMIT() asm volatile("cp.async.commit_group;")
#define CP_WAIT0()  asm volatile("cp.async.wait_group 0;" ::: "memory")

// smem: A_hi[128][256B] @0, A_lo @32KB, B tiles @64KB (Wl_hi, Wl_lo, Wr_hi, Wr_lo),
// stats @192KB (scale[128], shift[128]).
#define GEMM_SMEM (196608 + 1024)

// l==0: A rows come from xin (plain split). l>0: A rows = gelu(BN(g_out)) with
// stats from g_colsum/g_colsq and gamma/beta of layer l-1, then split.
__global__ void __launch_bounds__(512, 1) k_gemm_mma(int l, const float* __restrict__ xin,
                                                     const float* __restrict__ gamma,
                                                     const float* __restrict__ beta) {
    extern __shared__ __align__(16) char sm[];
    float* sstat = (float*)(sm + 196608);
    int tid = threadIdx.x;
    int row0 = blockIdx.x * 128;
    uint32_t sbase = (uint32_t)__cvta_generic_to_shared(sm);

    // B first (async, flies under A compute): 4 tiles, each 128 n-rows x 16 chunks
    for (int i = tid; i < 8192; i += 512) {
        int tile = i >> 11, j = i & 2047;
        int n = j >> 4, c = j & 15;
        int mm = tile >> 1;
        const __nv_bfloat16* src = (tile & 1) ? g_wlo : g_whi;
        uint32_t soff = (uint32_t)(65536 + tile * 32768 + n * 256 + ((c ^ (n & 7)) << 4));
        cp16(sbase + soff, src + ((l * 2 + mm) * D + n) * D + c * 8, 16);
    }
    CP_COMMIT();

    // BN stats -> smem (scale/shift per column)
    if (l > 0) {
        if (tid < 128) {
            const float invN = 1.f / (float)NN;
            float mu = g_colsum[tid] * invN;
            float var = g_colsq[tid] * invN - mu * mu;
            float sc = gamma[tid] * rsqrtf(var + BNEPS);
            sstat[tid] = sc;
            sstat[128 + tid] = beta[tid] - mu * sc;
        }
        __syncthreads();
    }

    // A stage: 4 chunks/thread; batch all 8 float4 loads first (MLP=8), then compute+STS
    const float* asrc = (l == 0) ? xin : g_out;
    {
        float4 va[4], vb[4];
#pragma unroll
        for (int k = 0; k < 4; k++) {
            int i = tid + 512 * k;
            int r = i >> 4, c = i & 15;
            int gr = row0 + r;
            if (gr < NN) {
                const float4* sp = (const float4*)(asrc + gr * D + c * 8);
                va[k] = sp[0];
                vb[k] = sp[1];
            } else {
                va[k] = make_float4(0.f, 0.f, 0.f, 0.f);
                vb[k] = make_float4(0.f, 0.f, 0.f, 0.f);
            }
        }
#pragma unroll
        for (int k = 0; k < 4; k++) {
            int i = tid + 512 * k;
            int r = i >> 4, c = i & 15;
            float e[8] = {va[k].x, va[k].y, va[k].z, va[k].w,
                          vb[k].x, vb[k].y, vb[k].z, vb[k].w};
            if (l > 0) {
                int col = c * 8;
#pragma unroll
                for (int j = 0; j < 8; j++) {
                    float y = fmaf(e[j], sstat[col + j], sstat[128 + col + j]);
                    e[j] = 0.5f * y * (1.f + erff(y * 0.70710678118654752f));
                }
            }
            uint4 hi, lo;
            split2(e[0], e[1], hi.x, lo.x);
            split2(e[2], e[3], hi.y, lo.y);
            split2(e[4], e[5], hi.z, lo.z);
            split2(e[6], e[7], hi.w, lo.w);
            uint32_t soff = (uint32_t)(r * 256 + ((c ^ (r & 7)) << 4));
            *(uint4*)(sm + soff) = hi;
            *(uint4*)(sm + 32768 + soff) = lo;
        }
    }
    CP_WAIT0();
    __syncthreads();

    int wid = tid >> 5, lane = tid & 31;
    int rg = wid & 3;          // row group: rows rg*32 .. rg*32+31
    int cg = wid >> 2;         // col group: 0,1 -> xl ; 2,3 -> xr
    int m = cg >> 1;
    int colbase = (cg & 1) * 64;
    uint32_t sA_h = sbase;
    uint32_t sA_l = sbase + 32768;
    uint32_t sB_h = sbase + 65536 + (uint32_t)(m * 2) * 32768u;
    uint32_t sB_l = sB_h + 32768;

    float acc[2][8][4];
#pragma unroll
    for (int mt = 0; mt < 2; mt++)
#pragma unroll
        for (int nt = 0; nt < 8; nt++)
#pragma unroll
            for (int q = 0; q < 4; q++) acc[mt][nt][q] = 0.f;

    // ldmatrix lane address components
    int a_r = (lane & 7) + ((lane >> 3) & 1) * 8;
    int a_c = lane >> 4;
    int b_n = (lane & 7) + (lane >> 4) * 8;
    int b_c = (lane >> 3) & 1;

#pragma unroll
    for (int ks = 0; ks < 8; ks++) {
        uint32_t ah[2][4], al[2][4];
#pragma unroll
        for (int mt = 0; mt < 2; mt++) {
            int r = rg * 32 + mt * 16 + a_r;
            int c = 2 * ks + a_c;
            uint32_t off = (uint32_t)(r * 256 + ((c ^ (r & 7)) << 4));
            ldsm4(ah[mt], sA_h + off);
            ldsm4(al[mt], sA_l + off);
        }
#pragma unroll
        for (int ng = 0; ng < 4; ng++) {
            int n = colbase + ng * 16 + b_n;
            int c = 2 * ks + b_c;
            uint32_t off = (uint32_t)(n * 256 + ((c ^ (n & 7)) << 4));
            uint32_t bh[4], bl[4];
            ldsm4(bh, sB_h + off);
            ldsm4(bl, sB_l + off);
            // term-outer order: same-acc dependency gap = 4 HMMA
            mma16816(acc[0][2 * ng], ah[0], &bh[0]);
            mma16816(acc[0][2 * ng + 1], ah[0], &bh[2]);
            mma16816(acc[1][2 * ng], ah[1], &bh[0]);
            mma16816(acc[1][2 * ng + 1], ah[1], &bh[2]);
            mma16816(acc[0][2 * ng], ah[0], &bl[0]);
            mma16816(acc[0][2 * ng + 1], ah[0], &bl[2]);
            mma16816(acc[1][2 * ng], ah[1], &bl[0]);
            mma16816(acc[1][2 * ng + 1], ah[1], &bl[2]);
            mma16816(acc[0][2 * ng], al[0], &bh[0]);
            mma16816(acc[0][2 * ng + 1], al[0], &bh[2]);
            mma16816(acc[1][2 * ng], al[1], &bh[0]);
            mma16816(acc[1][2 * ng + 1], al[1], &bh[2]);
        }
    }

    float* dst = m ? g_xr : g_xl;
    int g = lane >> 2, t = lane & 3;
#pragma unroll
    for (int mt = 0; mt < 2; mt++) {
#pragma unroll
        for (int nt = 0; nt < 8; nt++) {
            int r0 = row0 + rg * 32 + mt * 16 + g;
            int cc = colbase + nt * 8 + 2 * t;
            if (r0 < NN)
                *(float2*)(dst + r0 * D + cc) = make_float2(acc[mt][nt][0], acc[mt][nt][1]);
            if (r0 + 8 < NN)
                *(float2*)(dst + (r0 + 8) * D + cc) = make_float2(acc[mt][nt][2], acc[mt][nt][3]);
        }
    }
}

// ---------------- per-node GATv2: 16-lane groups, 2 edges in flight ----------------
__device__ __forceinline__ float lrelu(float z) {
    return z > 0.f ? z : NEG * z;
}

__global__ void __launch_bounds__(64) k_node(const float* __restrict__ att,
                                             const float* __restrict__ bias) {
    // fused: block 0 zeroes the BN column stats (read later by k_bn)
    if (blockIdx.x == 0) {
        int t = threadIdx.x;
        g_colsum[t] = 0.f;
        g_colsum[t + 64] = 0.f;
        g_colsq[t] = 0.f;
        g_colsq[t + 64] = 0.f;
    }
    int node = blockIdx.x * 2 + (threadIdx.x >> 5);
    if (node >= NN) return;
    int lane = threadIdx.x & 31;
    int l16 = lane & 15;
    int grp = lane >> 4;
    const unsigned gmask = 0xFFFFu << (grp << 4);
    int beg = g_off[node], end = g_off[node + 1];

    const float4* xr4 = (const float4*)(g_xr + node * 128 + l16 * 8);
    float4 xr0 = xr4[0], xr1 = xr4[1];
    const float4* at4 = (const float4*)(att + l16 * 8);
    float4 a0 = at4[0], a1 = at4[1];

    float m = -1e30f, sum = 0.f;
    float4 acc0 = make_float4(0.f, 0.f, 0.f, 0.f);
    float4 acc1 = make_float4(0.f, 0.f, 0.f, 0.f);

    for (int p = beg + grp; p < end; p += 2) {
        int s = g_srcs[p];
        const float4* v4 = (const float4*)(g_xl + s * 128 + l16 * 8);
        float4 v0 = v4[0], v1 = v4[1];
        float d = lrelu(v0.x + xr0.x) * a0.x;
        d = fmaf(lrelu(v0.y + xr0.y), a0.y, d);
        d = fmaf(lrelu(v0.z + xr0.z), a0.z, d);
        d = fmaf(lrelu(v0.w + xr0.w), a0.w, d);
        d = fmaf(lrelu(v1.x + xr1.x), a1.x, d);
        d = fmaf(lrelu(v1.y + xr1.y), a1.y, d);
        d = fmaf(lrelu(v1.z + xr1.z), a1.z, d);
        d = fmaf(lrelu(v1.w + xr1.w), a1.w, d);
#pragma unroll
        for (int o = 1; o < 16; o <<= 1) d += __shfl_xor_sync(gmask, d, o);
        float mn = fmaxf(m, d);
        float c = __expf(m - mn);
        float w = __expf(d - mn);
        sum = sum * c + w;
        acc0.x = fmaf(acc0.x, c, w * v0.x);
        acc0.y = fmaf(acc0.y, c, w * v0.y);
        acc0.z = fmaf(acc0.z, c, w * v0.z);
        acc0.w = fmaf(acc0.w, c, w * v0.w);
        acc1.x = fmaf(acc1.x, c, w * v1.x);
        acc1.y = fmaf(acc1.y, c, w * v1.y);
        acc1.z = fmaf(acc1.z, c, w * v1.z);
        acc1.w = fmaf(acc1.w, c, w * v1.w);
        m = mn;
    }
    __syncwarp();
    float mo = __shfl_xor_sync(0xffffffffu, m, 16);
    float so = __shfl_xor_sync(0xffffffffu, sum, 16);
    float ms = fmaxf(m, mo);
    float cme = __expf(m - ms);
    float sum_t = fmaf(so, __expf(mo - ms), sum * cme);
    acc0.x *= cme; acc0.y *= cme; acc0.z *= cme; acc0.w *= cme;
    acc1.x *= cme; acc1.y *= cme; acc1.z *= cme; acc1.w *= cme;
    acc0.x += __shfl_xor_sync(0xffffffffu, acc0.x, 16);
    acc0.y += __shfl_xor_sync(0xffffffffu, acc0.y, 16);
    acc0.z += __shfl_xor_sync(0xffffffffu, acc0.z, 16);
    acc0.w += __shfl_xor_sync(0xffffffffu, acc0.w, 16);
    acc1.x += __shfl_xor_sync(0xffffffffu, acc1.x, 16);
    acc1.y += __shfl_xor_sync(0xffffffffu, acc1.y, 16);
    acc1.z += __shfl_xor_sync(0xffffffffu, acc1.z, 16);
    acc1.w += __shfl_xor_sync(0xffffffffu, acc1.w, 16);
    if (grp == 0) {
        float inv = 1.f / (sum_t + 1e-16f);
        const float4* b4 = (const float4*)(bias + l16 * 8);
        float4 b0 = b4[0], b1 = b4[1];
        float4 o0, o1;
        o0.x = fmaf(acc0.x, inv, b0.x);
        o0.y = fmaf(acc0.y, inv, b0.y);
        o0.z = fmaf(acc0.z, inv, b0.z);
        o0.w = fmaf(acc0.w, inv, b0.w);
        o1.x = fmaf(acc1.x, inv, b1.x);
        o1.y = fmaf(acc1.y, inv, b1.y);
        o1.z = fmaf(acc1.z, inv, b1.z);
        o1.w = fmaf(acc1.w, inv, b1.w);
        float4* op = (float4*)(g_out + node * 128 + l16 * 8);
        op[0] = o0;
        op[1] = o1;
    }
}

// ---------------- BatchNorm stats ----------------
__global__ void k_bn() {
    int tid = threadIdx.x;
    int c4 = tid & 31;
    int rg = tid >> 5;
    float4 s = make_float4(0.f, 0.f, 0.f, 0.f);
    float4 q = make_float4(0.f, 0.f, 0.f, 0.f);
    for (int r = blockIdx.x * 8 + rg; r < NN; r += gridDim.x * 8) {
        float4 v = ((const float4*)g_out)[r * 32 + c4];
        s.x += v.x; s.y += v.y; s.z += v.z; s.w += v.w;
        q.x = fmaf(v.x, v.x, q.x); q.y = fmaf(v.y, v.y, q.y);
        q.z = fmaf(v.z, v.z, q.z); q.w = fmaf(v.w, v.w, q.w);
    }
    __shared__ float shs[8][32][4];
    __shared__ float shq[8][32][4];
    shs[rg][c4][0] = s.x; shs[rg][c4][1] = s.y; shs[rg][c4][2] = s.z; shs[rg][c4][3] = s.w;
    shq[rg][c4][0] = q.x; shq[rg][c4][1] = q.y; shq[rg][c4][2] = q.z; shq[rg][c4][3] = q.w;
    __syncthreads();
    if (tid < 128) {
        int col = tid;
        int cc4 = col >> 2, ce = col & 3;
        float ts = 0.f, tq = 0.f;
#pragma unroll
        for (int g = 0; g < 8; g++) {
            ts += shs[g][cc4][ce];
            tq += shq[g][cc4][ce];
        }
        atomicAdd(&g_colsum[col], ts);
        atomicAdd(&g_colsq[col], tq);
    }
}

// final-layer BN + erf-GELU -> fp32 d_out
__global__ void k_bnapply(const float* __restrict__ gamma,
                          const float* __restrict__ beta,
                          float* __restrict__ dptr) {
    __shared__ float ssc[128], ssh[128];
    int tid = threadIdx.x;
    if (tid < 128) {
        const float invN = 1.f / (float)NN;
        float mu = g_colsum[tid] * invN;
        float var = g_colsq[tid] * invN - mu * mu;
        float sc = gamma[tid] * rsqrtf(var + BNEPS);
        ssc[tid] = sc;
        ssh[tid] = beta[tid] - mu * sc;
    }
    __syncthreads();
    int i = blockIdx.x * 256 + tid;  // over NN*32 float4s
    if (i >= NN * 32) return;
    int c4 = (i & 31) * 4;
    float4 v = ((const float4*)g_out)[i];
    float o[4];
    float vin[4] = {v.x, v.y, v.z, v.w};
#pragma unroll
    for (int c = 0; c < 4; c++) {
        float y = fmaf(vin[c], ssc[c4 + c], ssh[c4 + c]);
        o[c] = 0.5f * y * (1.f + erff(y * 0.70710678118654752f));
    }
    ((float4*)dptr)[i] = make_float4(o[0], o[1], o[2], o[3]);
}

// ---------------- launch ----------------
extern "C" void kernel_launch(void* const* d_in, const int* in_sizes, int n_in,
                              void* d_out, int out_size) {
    const float* x = (const float*)d_in[0];
    const int* ei = (const int*)d_in[1];
    const float* Wl = (const float*)d_in[2];
    const float* Wr = (const float*)d_in[3];
    const float* att = (const float*)d_in[4];
    const float* bias = (const float*)d_in[5];
    const float* gamma = (const float*)d_in[6];
    const float* beta = (const float*)d_in[7];
    float* outp = (float*)d_out;

    cudaFuncSetAttribute(k_gemm_mma, cudaFuncAttributeMaxDynamicSharedMemorySize, GEMM_SMEM);

    const int gemm_blocks = (NN + 127) / 128;

    // launches 1-3: cvt_w, detect+zero, hist; 4: layer-0 GEMM (profiled slot)
    k_cvt_w<<<(3 * 2 * D * D + 255) / 256, 256>>>(Wl, Wr);
    k_detect_zero<<<SB, 256>>>(ei);
    k_hist<<<(NE + 255) / 256, 256>>>(ei);
    k_gemm_mma<<<gemm_blocks, 512, GEMM_SMEM>>>(0, x, nullptr, nullptr);

    // CSR by dst (remaining stages)
    k_part<<<SB, 256>>>();
    k_scanpart<<<1, 256>>>();
    k_off<<<SB, 256>>>();
    k_scatter<<<(NE + 255) / 256, 256>>>(ei);

    for (int l = 0; l < 3; l++) {
        if (l > 0)
            k_gemm_mma<<<gemm_blocks, 512, GEMM_SMEM>>>(l, nullptr,
                                                        gamma + (l - 1) * D,
                                                        beta + (l - 1) * D);
        k_node<<<(NN + 1) / 2, 64>>>(att + l * D, bias + l * D);
        k_bn<<<296, 256>>>();
    }
    // final BN+GELU -> output
    k_bnapply<<<(NN * 32 + 255) / 256, 256>>>(gamma + 2 * D, beta + 2 * D, outp);
}

// round 16
// speedup vs baseline: 4.5436x; 1.0338x over previous
#include <cuda_runtime.h>
#include <cuda_bf16.h>
#include <math.h>
#include <cstdint>

#define NN 50000
#define NE 800000
#define D  128
#define NEG 0.2f
#define BNEPS 1e-5f
#define SB 196   // scan blocks (196*256 = 50176 >= NN)

// ---------------- static device scratch (no allocations allowed) ----------------
__device__ float g_xl[NN * D];
__device__ float g_xr[NN * D];
__device__ float g_out[NN * D];
__device__ __nv_bfloat16 g_whi[3 * 2 * D * D];   // W^T per layer/matrix: [lm][n][k]
__device__ __nv_bfloat16 g_wlo[3 * 2 * D * D];
__device__ int   g_srcs[NE];
__device__ int   g_off[NN + 1];
__device__ int   g_cur[NN];
__device__ int   g_cnt[NN];
__device__ int   g_part[256];
__device__ float g_colsum[D];
__device__ float g_colsq[D];
__device__ int   g_is64;

// ---------------- edge dtype probe + counter zero (fused) ----------------
__global__ void k_detect_zero(const int* __restrict__ w) {
    int i = blockIdx.x * 256 + threadIdx.x;
    if (i < NN) g_cnt[i] = 0;
    if (i == 0) {
        int allz = 1;
        for (int j = 1; j < 64; j += 2)
            if (w[j] != 0) allz = 0;
        g_is64 = allz;
    }
}

__device__ __forceinline__ int edge_at(const int* __restrict__ w, int pos, int is64) {
    return is64 ? w[(long long)pos * 2] : w[pos];
}

// ---------------- CSR build ----------------
__global__ void k_hist(const int* __restrict__ ei) {
    int e = blockIdx.x * 256 + threadIdx.x;
    if (e < NE) atomicAdd(&g_cnt[edge_at(ei, NE + e, g_is64)], 1);
}

__global__ void k_part() {
    __shared__ int sh[256];
    int tid = threadIdx.x;
    int i = blockIdx.x * 256 + tid;
    int v = (i < NN) ? g_cnt[i] : 0;
    sh[tid] = v;
    __syncthreads();
    for (int o = 128; o > 0; o >>= 1) {
        if (tid < o) sh[tid] += sh[tid + o];
        __syncthreads();
    }
    if (tid == 0) g_part[blockIdx.x] = sh[0];
}

// local inclusive scan + (recomputed) block base -> offsets; scanpart folded in
__global__ void k_off() {
    __shared__ int sh[256];
    __shared__ int shp[256];
    int tid = threadIdx.x;
    // scan the 196 block partials locally
    int pv = (tid < SB) ? g_part[tid] : 0;
    shp[tid] = pv;
    __syncthreads();
    for (int o = 1; o < 256; o <<= 1) {
        int t = (tid >= o) ? shp[tid - o] : 0;
        __syncthreads();
        shp[tid] += t;
        __syncthreads();
    }
    int base = shp[blockIdx.x] - g_part[blockIdx.x];  // exclusive prefix of this block
    // local scan of counts
    int i = blockIdx.x * 256 + tid;
    int v = (i < NN) ? g_cnt[i] : 0;
    sh[tid] = v;
    __syncthreads();
    for (int o = 1; o < 256; o <<= 1) {
        int t = (tid >= o) ? sh[tid - o] : 0;
        __syncthreads();
        sh[tid] += t;
        __syncthreads();
    }
    int excl = sh[tid] - v + base;
    if (i < NN) {
        g_off[i] = excl;
        g_cur[i] = excl;
        if (i == NN - 1) g_off[NN] = excl + v;
    }
}

__global__ void k_scatter(const int* __restrict__ ei) {
    int e = blockIdx.x * 256 + threadIdx.x;
    if (e < NE) {
        int is64 = g_is64;
        int src = edge_at(ei, e, is64);
        int dst = edge_at(ei, NE + e, is64);
        int pos = atomicAdd(&g_cur[dst], 1);
        g_srcs[pos] = src;
    }
}

// ---------------- conversions (fp32 -> split bf16) ----------------
__device__ __forceinline__ void split2(float a, float b, uint32_t& hi, uint32_t& lo) {
    __nv_bfloat16 ha = __float2bfloat16(a);
    __nv_bfloat16 hb = __float2bfloat16(b);
    __nv_bfloat16 la = __float2bfloat16(a - __bfloat162float(ha));
    __nv_bfloat16 lb = __float2bfloat16(b - __bfloat162float(hb));
    hi = (uint32_t)__bfloat16_as_ushort(ha) | ((uint32_t)__bfloat16_as_ushort(hb) << 16);
    lo = (uint32_t)__bfloat16_as_ushort(la) | ((uint32_t)__bfloat16_as_ushort(lb) << 16);
}

// W^T split: wt[lm][n][k] = W[l][k][n]   (lm = l*2+m; m: 0=Wl, 1=Wr)
__global__ void k_cvt_w(const float* __restrict__ Wl, const float* __restrict__ Wr) {
    int idx = blockIdx.x * 256 + threadIdx.x;
    if (idx >= 3 * 2 * D * D) return;
    int lm = idx >> 14, r = idx & 16383;
    int n = r >> 7, k = r & 127;
    int l = lm >> 1, m = lm & 1;
    const float* W = m ? Wr : Wl;
    float v = W[l * D * D + k * D + n];
    __nv_bfloat16 h = __float2bfloat16(v);
    __nv_bfloat16 lo = __float2bfloat16(v - __bfloat162float(h));
    g_whi[idx] = h;
    g_wlo[idx] = lo;
}

// ---------------- tensor-core dual GEMM: fused BN/GELU/split A-stage + cp.async B ----------------
__device__ __forceinline__ void mma16816(float* c, const uint32_t* a, const uint32_t* b) {
    asm volatile(
        "mma.sync.aligned.m16n8k16.row.col.f32.bf16.bf16.f32 "
        "{%0,%1,%2,%3}, {%4,%5,%6,%7}, {%8,%9}, {%0,%1,%2,%3};"
        : "+f"(c[0]), "+f"(c[1]), "+f"(c[2]), "+f"(c[3])
        : "r"(a[0]), "r"(a[1]), "r"(a[2]), "r"(a[3]), "r"(b[0]), "r"(b[1]));
}

__device__ __forceinline__ void ldsm4(uint32_t* r, uint32_t addr) {
    asm volatile(
        "ldmatrix.sync.aligned.m8n8.x4.shared.b16 {%0,%1,%2,%3}, [%4];"
        : "=r"(r[0]), "=r"(r[1]), "=r"(r[2]), "=r"(r[3]) : "r"(addr));
}

__device__ __forceinline__ void cp16(uint32_t dst, const void* src, int sz) {
    asm volatile("cp.async.cg.shared.global [%0], [%1], 16, %2;"
                 :: "r"(dst), "l"(src), "r"(sz));
}
#define CP_COMMIT() asm volatile("cp.async.commit_group;")
#define CP_WAIT0()  asm volatile("cp.async.wait_group 0;" ::: "memory")

// smem: A_hi[128][256B] @0, A_lo @32KB, B tiles @64KB (Wl_hi, Wl_lo, Wr_hi, Wr_lo),
// stats @192KB (scale[128], shift[128]).
#define GEMM_SMEM (196608 + 1024)

// l==0: A rows come from xin (plain split). l>0: A rows = gelu(BN(g_out)) with
// stats from g_colsum/g_colsq and gamma/beta of layer l-1, then split.
__global__ void __launch_bounds__(512, 1) k_gemm_mma(int l, const float* __restrict__ xin,
                                                     const float* __restrict__ gamma,
                                                     const float* __restrict__ beta) {
    extern __shared__ __align__(16) char sm[];
    float* sstat = (float*)(sm + 196608);
    int tid = threadIdx.x;
    int row0 = blockIdx.x * 128;
    uint32_t sbase = (uint32_t)__cvta_generic_to_shared(sm);

    // B first (async, flies under A compute): 4 tiles, each 128 n-rows x 16 chunks
    for (int i = tid; i < 8192; i += 512) {
        int tile = i >> 11, j = i & 2047;
        int n = j >> 4, c = j & 15;
        int mm = tile >> 1;
        const __nv_bfloat16* src = (tile & 1) ? g_wlo : g_whi;
        uint32_t soff = (uint32_t)(65536 + tile * 32768 + n * 256 + ((c ^ (n & 7)) << 4));
        cp16(sbase + soff, src + ((l * 2 + mm) * D + n) * D + c * 8, 16);
    }
    CP_COMMIT();

    // BN stats -> smem (scale/shift per column)
    if (l > 0) {
        if (tid < 128) {
            const float invN = 1.f / (float)NN;
            float mu = g_colsum[tid] * invN;
            float var = g_colsq[tid] * invN - mu * mu;
            float sc = gamma[tid] * rsqrtf(var + BNEPS);
            sstat[tid] = sc;
            sstat[128 + tid] = beta[tid] - mu * sc;
        }
        __syncthreads();
    }

    // A stage: 4 chunks/thread; batch all 8 float4 loads first (MLP=8), then compute+STS
    const float* asrc = (l == 0) ? xin : g_out;
    {
        float4 va[4], vb[4];
#pragma unroll
        for (int k = 0; k < 4; k++) {
            int i = tid + 512 * k;
            int r = i >> 4, c = i & 15;
            int gr = row0 + r;
            if (gr < NN) {
                const float4* sp = (const float4*)(asrc + gr * D + c * 8);
                va[k] = sp[0];
                vb[k] = sp[1];
            } else {
                va[k] = make_float4(0.f, 0.f, 0.f, 0.f);
                vb[k] = make_float4(0.f, 0.f, 0.f, 0.f);
            }
        }
#pragma unroll
        for (int k = 0; k < 4; k++) {
            int i = tid + 512 * k;
            int r = i >> 4, c = i & 15;
            float e[8] = {va[k].x, va[k].y, va[k].z, va[k].w,
                          vb[k].x, vb[k].y, vb[k].z, vb[k].w};
            if (l > 0) {
                int col = c * 8;
#pragma unroll
                for (int j = 0; j < 8; j++) {
                    float y = fmaf(e[j], sstat[col + j], sstat[128 + col + j]);
                    e[j] = 0.5f * y * (1.f + erff(y * 0.70710678118654752f));
                }
            }
            uint4 hi, lo;
            split2(e[0], e[1], hi.x, lo.x);
            split2(e[2], e[3], hi.y, lo.y);
            split2(e[4], e[5], hi.z, lo.z);
            split2(e[6], e[7], hi.w, lo.w);
            uint32_t soff = (uint32_t)(r * 256 + ((c ^ (r & 7)) << 4));
            *(uint4*)(sm + soff) = hi;
            *(uint4*)(sm + 32768 + soff) = lo;
        }
    }
    CP_WAIT0();
    __syncthreads();

    int wid = tid >> 5, lane = tid & 31;
    int rg = wid & 3;          // row group: rows rg*32 .. rg*32+31
    int cg = wid >> 2;         // col group: 0,1 -> xl ; 2,3 -> xr
    int m = cg >> 1;
    int colbase = (cg & 1) * 64;
    uint32_t sA_h = sbase;
    uint32_t sA_l = sbase + 32768;
    uint32_t sB_h = sbase + 65536 + (uint32_t)(m * 2) * 32768u;
    uint32_t sB_l = sB_h + 32768;

    float acc[2][8][4];
#pragma unroll
    for (int mt = 0; mt < 2; mt++)
#pragma unroll
        for (int nt = 0; nt < 8; nt++)
#pragma unroll
            for (int q = 0; q < 4; q++) acc[mt][nt][q] = 0.f;

    // ldmatrix lane address components
    int a_r = (lane & 7) + ((lane >> 3) & 1) * 8;
    int a_c = lane >> 4;
    int b_n = (lane & 7) + (lane >> 4) * 8;
    int b_c = (lane >> 3) & 1;

#pragma unroll
    for (int ks = 0; ks < 8; ks++) {
        uint32_t ah[2][4], al[2][4];
#pragma unroll
        for (int mt = 0; mt < 2; mt++) {
            int r = rg * 32 + mt * 16 + a_r;
            int c = 2 * ks + a_c;
            uint32_t off = (uint32_t)(r * 256 + ((c ^ (r & 7)) << 4));
            ldsm4(ah[mt], sA_h + off);
            ldsm4(al[mt], sA_l + off);
        }
#pragma unroll
        for (int ng = 0; ng < 4; ng++) {
            int n = colbase + ng * 16 + b_n;
            int c = 2 * ks + b_c;
            uint32_t off = (uint32_t)(n * 256 + ((c ^ (n & 7)) << 4));
            uint32_t bh[4], bl[4];
            ldsm4(bh, sB_h + off);
            ldsm4(bl, sB_l + off);
            // term-outer order: same-acc dependency gap = 4 HMMA
            mma16816(acc[0][2 * ng], ah[0], &bh[0]);
            mma16816(acc[0][2 * ng + 1], ah[0], &bh[2]);
            mma16816(acc[1][2 * ng], ah[1], &bh[0]);
            mma16816(acc[1][2 * ng + 1], ah[1], &bh[2]);
            mma16816(acc[0][2 * ng], ah[0], &bl[0]);
            mma16816(acc[0][2 * ng + 1], ah[0], &bl[2]);
            mma16816(acc[1][2 * ng], ah[1], &bl[0]);
            mma16816(acc[1][2 * ng + 1], ah[1], &bl[2]);
            mma16816(acc[0][2 * ng], al[0], &bh[0]);
            mma16816(acc[0][2 * ng + 1], al[0], &bh[2]);
            mma16816(acc[1][2 * ng], al[1], &bh[0]);
            mma16816(acc[1][2 * ng + 1], al[1], &bh[2]);
        }
    }

    float* dst = m ? g_xr : g_xl;
    int g = lane >> 2, t = lane & 3;
#pragma unroll
    for (int mt = 0; mt < 2; mt++) {
#pragma unroll
        for (int nt = 0; nt < 8; nt++) {
            int r0 = row0 + rg * 32 + mt * 16 + g;
            int cc = colbase + nt * 8 + 2 * t;
            if (r0 < NN)
                *(float2*)(dst + r0 * D + cc) = make_float2(acc[mt][nt][0], acc[mt][nt][1]);
            if (r0 + 8 < NN)
                *(float2*)(dst + (r0 + 8) * D + cc) = make_float2(acc[mt][nt][2], acc[mt][nt][3]);
        }
    }
}

// ---------------- per-node GATv2: 16-lane groups, src-index prefetch ----------------
__device__ __forceinline__ float lrelu(float z) {
    return z > 0.f ? z : NEG * z;
}

__global__ void __launch_bounds__(64) k_node(const float* __restrict__ att,
                                             const float* __restrict__ bias) {
    // fused: block 0 zeroes the BN column stats (read later by k_bn)
    if (blockIdx.x == 0) {
        int t = threadIdx.x;
        g_colsum[t] = 0.f;
        g_colsum[t + 64] = 0.f;
        g_colsq[t] = 0.f;
        g_colsq[t + 64] = 0.f;
    }
    int node = blockIdx.x * 2 + (threadIdx.x >> 5);
    if (node >= NN) return;
    int lane = threadIdx.x & 31;
    int l16 = lane & 15;
    int grp = lane >> 4;
    const unsigned gmask = 0xFFFFu << (grp << 4);
    int beg = g_off[node], end = g_off[node + 1];

    const float4* xr4 = (const float4*)(g_xr + node * 128 + l16 * 8);
    float4 xr0 = xr4[0], xr1 = xr4[1];
    const float4* at4 = (const float4*)(att + l16 * 8);
    float4 a0 = at4[0], a1 = at4[1];

    float m = -1e30f, sum = 0.f;
    float4 acc0 = make_float4(0.f, 0.f, 0.f, 0.f);
    float4 acc1 = make_float4(0.f, 0.f, 0.f, 0.f);

    // src-index prefetch: breaks the g_srcs[p] -> xl[s] serial chain.
    // clamped index keeps the load in-bounds without a branch.
    int last = end - 1;
    int p = beg + grp;
    int s = g_srcs[(p <= last) ? p : last];
    for (; p < end; p += 2) {
        int pn = p + 2;
        int sn = g_srcs[(pn <= last) ? pn : last];
        const float4* v4 = (const float4*)(g_xl + s * 128 + l16 * 8);
        float4 v0 = v4[0], v1 = v4[1];
        float d = lrelu(v0.x + xr0.x) * a0.x;
        d = fmaf(lrelu(v0.y + xr0.y), a0.y, d);
        d = fmaf(lrelu(v0.z + xr0.z), a0.z, d);
        d = fmaf(lrelu(v0.w + xr0.w), a0.w, d);
        d = fmaf(lrelu(v1.x + xr1.x), a1.x, d);
        d = fmaf(lrelu(v1.y + xr1.y), a1.y, d);
        d = fmaf(lrelu(v1.z + xr1.z), a1.z, d);
        d = fmaf(lrelu(v1.w + xr1.w), a1.w, d);
#pragma unroll
        for (int o = 1; o < 16; o <<= 1) d += __shfl_xor_sync(gmask, d, o);
        float mn = fmaxf(m, d);
        float c = __expf(m - mn);
        float w = __expf(d - mn);
        sum = sum * c + w;
        acc0.x = fmaf(acc0.x, c, w * v0.x);
        acc0.y = fmaf(acc0.y, c, w * v0.y);
        acc0.z = fmaf(acc0.z, c, w * v0.z);
        acc0.w = fmaf(acc0.w, c, w * v0.w);
        acc1.x = fmaf(acc1.x, c, w * v1.x);
        acc1.y = fmaf(acc1.y, c, w * v1.y);
        acc1.z = fmaf(acc1.z, c, w * v1.z);
        acc1.w = fmaf(acc1.w, c, w * v1.w);
        m = mn;
        s = sn;
    }
    __syncwarp();
    float mo = __shfl_xor_sync(0xffffffffu, m, 16);
    float so = __shfl_xor_sync(0xffffffffu, sum, 16);
    float ms = fmaxf(m, mo);
    float cme = __expf(m - ms);
    float sum_t = fmaf(so, __expf(mo - ms), sum * cme);
    acc0.x *= cme; acc0.y *= cme; acc0.z *= cme; acc0.w *= cme;
    acc1.x *= cme; acc1.y *= cme; acc1.z *= cme; acc1.w *= cme;
    acc0.x += __shfl_xor_sync(0xffffffffu, acc0.x, 16);
    acc0.y += __shfl_xor_sync(0xffffffffu, acc0.y, 16);
    acc0.z += __shfl_xor_sync(0xffffffffu, acc0.z, 16);
    acc0.w += __shfl_xor_sync(0xffffffffu, acc0.w, 16);
    acc1.x += __shfl_xor_sync(0xffffffffu, acc1.x, 16);
    acc1.y += __shfl_xor_sync(0xffffffffu, acc1.y, 16);
    acc1.z += __shfl_xor_sync(0xffffffffu, acc1.z, 16);
    acc1.w += __shfl_xor_sync(0xffffffffu, acc1.w, 16);
    if (grp == 0) {
        float inv = 1.f / (sum_t + 1e-16f);
        const float4* b4 = (const float4*)(bias + l16 * 8);
        float4 b0 = b4[0], b1 = b4[1];
        float4 o0, o1;
        o0.x = fmaf(acc0.x, inv, b0.x);
        o0.y = fmaf(acc0.y, inv, b0.y);
        o0.z = fmaf(acc0.z, inv, b0.z);
        o0.w = fmaf(acc0.w, inv, b0.w);
        o1.x = fmaf(acc1.x, inv, b1.x);
        o1.y = fmaf(acc1.y, inv, b1.y);
        o1.z = fmaf(acc1.z, inv, b1.z);
        o1.w = fmaf(acc1.w, inv, b1.w);
        float4* op = (float4*)(g_out + node * 128 + l16 * 8);
        op[0] = o0;
        op[1] = o1;
    }
}

// ---------------- BatchNorm stats ----------------
__global__ void k_bn() {
    int tid = threadIdx.x;
    int c4 = tid & 31;
    int rg = tid >> 5;
    float4 s = make_float4(0.f, 0.f, 0.f, 0.f);
    float4 q = make_float4(0.f, 0.f, 0.f, 0.f);
    for (int r = blockIdx.x * 8 + rg; r < NN; r += gridDim.x * 8) {
        float4 v = ((const float4*)g_out)[r * 32 + c4];
        s.x += v.x; s.y += v.y; s.z += v.z; s.w += v.w;
        q.x = fmaf(v.x, v.x, q.x); q.y = fmaf(v.y, v.y, q.y);
        q.z = fmaf(v.z, v.z, q.z); q.w = fmaf(v.w, v.w, q.w);
    }
    __shared__ float shs[8][32][4];
    __shared__ float shq[8][32][4];
    shs[rg][c4][0] = s.x; shs[rg][c4][1] = s.y; shs[rg][c4][2] = s.z; shs[rg][c4][3] = s.w;
    shq[rg][c4][0] = q.x; shq[rg][c4][1] = q.y; shq[rg][c4][2] = q.z; shq[rg][c4][3] = q.w;
    __syncthreads();
    if (tid < 128) {
        int col = tid;
        int cc4 = col >> 2, ce = col & 3;
        float ts = 0.f, tq = 0.f;
#pragma unroll
        for (int g = 0; g < 8; g++) {
            ts += shs[g][cc4][ce];
            tq += shq[g][cc4][ce];
        }
        atomicAdd(&g_colsum[col], ts);
        atomicAdd(&g_colsq[col], tq);
    }
}

// final-layer BN + erf-GELU -> fp32 d_out
__global__ void k_bnapply(const float* __restrict__ gamma,
                          const float* __restrict__ beta,
                          float* __restrict__ dptr) {
    __shared__ float ssc[128], ssh[128];
    int tid = threadIdx.x;
    if (tid < 128) {
        const float invN = 1.f / (float)NN;
        float mu = g_colsum[tid] * invN;
        float var = g_colsq[tid] * invN - mu * mu;
        float sc = gamma[tid] * rsqrtf(var + BNEPS);
        ssc[tid] = sc;
        ssh[tid] = beta[tid] - mu * sc;
    }
    __syncthreads();
    int i = blockIdx.x * 256 + tid;  // over NN*32 float4s
    if (i >= NN * 32) return;
    int c4 = (i & 31) * 4;
    float4 v = ((const float4*)g_out)[i];
    float o[4];
    float vin[4] = {v.x, v.y, v.z, v.w};
#pragma unroll
    for (int c = 0; c < 4; c++) {
        float y = fmaf(vin[c], ssc[c4 + c], ssh[c4 + c]);
        o[c] = 0.5f * y * (1.f + erff(y * 0.70710678118654752f));
    }
    ((float4*)dptr)[i] = make_float4(o[0], o[1], o[2], o[3]);
}

// ---------------- launch ----------------
extern "C" void kernel_launch(void* const* d_in, const int* in_sizes, int n_in,
                              void* d_out, int out_size) {
    const float* x = (const float*)d_in[0];
    const int* ei = (const int*)d_in[1];
    const float* Wl = (const float*)d_in[2];
    const float* Wr = (const float*)d_in[3];
    const float* att = (const float*)d_in[4];
    const float* bias = (const float*)d_in[5];
    const float* gamma = (const float*)d_in[6];
    const float* beta = (const float*)d_in[7];
    float* outp = (float*)d_out;

    cudaFuncSetAttribute(k_gemm_mma, cudaFuncAttributeMaxDynamicSharedMemorySize, GEMM_SMEM);

    const int gemm_blocks = (NN + 127) / 128;

    // launches 1-3: cvt_w, detect+zero, hist; 4: layer-0 GEMM (profiled slot)
    k_cvt_w<<<(3 * 2 * D * D + 255) / 256, 256>>>(Wl, Wr);
    k_detect_zero<<<SB, 256>>>(ei);
    k_hist<<<(NE + 255) / 256, 256>>>(ei);
    k_gemm_mma<<<gemm_blocks, 512, GEMM_SMEM>>>(0, x, nullptr, nullptr);

    // CSR by dst (remaining stages; scanpart folded into k_off)
    k_part<<<SB, 256>>>();
    k_off<<<SB, 256>>>();
    k_scatter<<<(NE + 255) / 256, 256>>>(ei);

    for (int l = 0; l < 3; l++) {
        if (l > 0)
            k_gemm_mma<<<gemm_blocks, 512, GEMM_SMEM>>>(l, nullptr,
                                                        gamma + (l - 1) * D,
                                                        beta + (l - 1) * D);
        k_node<<<(NN + 1) / 2, 64>>>(att + l * D, bias + l * D);
        k_bn<<<296, 256>>>();
    }
    // final BN+GELU -> output
    k_bnapply<<<(NN * 32 + 255) / 256, 256>>>(gamma + 2 * D, beta + 2 * D, outp);
}